// round 4
// baseline (speedup 1.0000x reference)
#include <cuda_runtime.h>
#include <stdint.h>

#define B_   4096
#define F_   1024
#define H_   256
#define C_   10
#define T_   24
#define RPB  4

// ---- transposed weights (device globals; no allocation) ----
__device__ __align__(16) float g_W1T[F_ * H_];   // [f][j]
__device__ __align__(16) float g_W2T[H_ * H_];   // [k][j]
__device__ __align__(16) float g_W3T[H_ * H_];   // [k][j]

// ---- packed f32x2 helpers (Blackwell) ----
__device__ __forceinline__ unsigned long long pk2(float lo, float hi) {
    unsigned long long r;
    asm("mov.b64 %0, {%1, %2};" : "=l"(r) : "f"(lo), "f"(hi));
    return r;
}
__device__ __forceinline__ void upk2(unsigned long long v, float& lo, float& hi) {
    asm("mov.b64 {%0, %1}, %2;" : "=f"(lo), "=f"(hi) : "l"(v));
}
__device__ __forceinline__ void addx2(unsigned long long& a, unsigned long long b) {
    asm("add.rn.f32x2 %0, %1, %2;" : "=l"(a) : "l"(a), "l"(b));
}
__device__ __forceinline__ void pref1(const char* p) {
    asm volatile("prefetch.global.L1 [%0];" :: "l"(p));
}

// per-row-group barrier (64 threads, ids 1..RPB)
#define BARG() asm volatile("bar.sync %0, 64;" :: "r"(barid) : "memory")

// warp exclusive scan; also returns warp total
__device__ __forceinline__ int wscan_excl(int v, int lane, int& total) {
    int inc = v;
#pragma unroll
    for (int off = 1; off < 32; off <<= 1) {
        int y = __shfl_up_sync(0xffffffffu, inc, off);
        if (lane >= off) inc += y;
    }
    total = __shfl_sync(0xffffffffu, inc, 31);
    return inc - v;
}

// ============================================================
// Tiled transpose of W1/W2/W3 into device globals.
// ============================================================
__global__ void __launch_bounds__(256) transpose_all(
    const float* __restrict__ W1, const float* __restrict__ W2,
    const float* __restrict__ W3) {
    __shared__ float tile[32][33];
    const int zi = blockIdx.z;
    const float* src = (zi == 0) ? W1 : ((zi == 1) ? W2 : W3);
    float* dst = (zi == 0) ? g_W1T : ((zi == 1) ? g_W2T : g_W3T);
    const int C = (zi == 0) ? F_ : H_;
    const int R = H_;
    if ((int)(blockIdx.x * 32) >= C) return;

    const int x = blockIdx.x * 32 + threadIdx.x;
    const int y0 = blockIdx.y * 32;
#pragma unroll
    for (int dy = threadIdx.y; dy < 32; dy += 8)
        tile[dy][threadIdx.x] = src[(size_t)(y0 + dy) * C + x];
    __syncthreads();
    const int x2 = y0 + threadIdx.x;
#pragma unroll
    for (int dy = threadIdx.y; dy < 32; dy += 8)
        dst[(size_t)(blockIdx.x * 32 + dy) * R + x2] = tile[threadIdx.x][dy];
}

// ============================================================
// gather over prescaled byte offsets, 4 accumulator chains, unroll 4
// ============================================================
__device__ __forceinline__ void gatherN(const char* __restrict__ wb,
                                        const uint32_t* __restrict__ lst, int n,
                                        unsigned long long& a01, unsigned long long& a23,
                                        unsigned long long& b01, unsigned long long& b23) {
    int e = 0;
    for (; e + 4 <= n; e += 4) {
        uint4 o = *(const uint4*)(lst + e);
        ulonglong2 w0 = *(const ulonglong2*)(wb + o.x);
        ulonglong2 w1 = *(const ulonglong2*)(wb + o.y);
        ulonglong2 w2 = *(const ulonglong2*)(wb + o.z);
        ulonglong2 w3 = *(const ulonglong2*)(wb + o.w);
        addx2(a01, w0.x); addx2(a23, w0.y);
        addx2(b01, w1.x); addx2(b23, w1.y);
        addx2(a01, w2.x); addx2(a23, w2.y);
        addx2(b01, w3.x); addx2(b23, w3.y);
    }
    for (; e < n; e++) {
        ulonglong2 w = *(const ulonglong2*)(wb + lst[e]);
        addx2(a01, w.x); addx2(a23, w.y);
    }
}

// ============================================================
// Main fused kernel: encoder + 24-step SNN + folded linear readout.
// 256 threads = RPB(4) independent 64-thread row groups (named barriers).
// Thread g owns hidden units [4g,4g+3]; LIF state in registers.
// Phase 1: W1 gather (L1-prefetched one step ahead) -> z1 (ballot list).
// Phase 2: dual gather W2[z1] + W3[z1]; z2 list; build next enc list.
// Phase 3: gather W3[z2]; fold readout; prefetch next W1 columns.
// ============================================================
__global__ void __launch_bounds__(256, 4)
snn_kernel(const float* __restrict__ x,
           const float* __restrict__ b1, const float* __restrict__ b2,
           const float* __restrict__ b3, const float* __restrict__ Wli,
           float* __restrict__ out) {
    __shared__ uint32_t s_bits[RPB][T_][32];                 // 12 KB
    __shared__ __align__(16) uint16_t s_l1[2][RPB][512];     // 8 KB (sorted enc lists)
    __shared__ __align__(16) uint32_t s_lz1[RPB][H_];        // 4 KB (z1 byte offsets)
    __shared__ __align__(16) uint32_t s_lz2[RPB][H_];        // 4 KB (z2 byte offsets)
    __shared__ int s_cntA[2][RPB];
    __shared__ int s_cnt1[RPB];
    __shared__ int s_cnt2[RPB];
    __shared__ float s_part[RPB][2][C_];

    const int tid = threadIdx.x;
    const int r = tid >> 6;
    const int g = tid & 63;
    const int lane = tid & 31;
    const int j0 = g * 4;
    const int barid = r + 1;
    const int row = blockIdx.x * RPB + r;
    const float* xrow = x + (size_t)row * F_;

    // ---- zero this row's bitmaps & counters ----
    for (int i = g; i < T_ * 32; i += 64) ((uint32_t*)s_bits[r])[i] = 0;
    if (g == 0) { s_cnt1[r] = 0; s_cnt2[r] = 0; }
    BARG();

    // ---- fused encoder -> scatter spikes into per-step bitmaps ----
    {
        const uint32_t mybit = 1u << (g & 31);
        const int wbase = g >> 5;
#pragma unroll 1
        for (int m0 = 0; m0 < 16; m0 += 4) {
            float xv[4], vv[4];
            uint32_t mk[4];
#pragma unroll
            for (int j = 0; j < 4; j++) {
                xv[j] = xrow[g + 64 * (m0 + j)];
                vv[j] = 0.0f; mk[j] = 0u;
            }
#pragma unroll
            for (int t = 0; t < T_; t++) {
#pragma unroll
                for (int j = 0; j < 4; j++) {
                    vv[j] = vv[j] + 0.1f * (xv[j] - vv[j]);
                    if (vv[j] > 1.0f) { mk[j] |= (1u << t); vv[j] = 0.0f; }
                }
            }
#pragma unroll
            for (int j = 0; j < 4; j++) {
                uint32_t m = mk[j];
                const int w = wbase + 2 * (m0 + j);
                while (m) {
                    int t = __ffs(m) - 1; m &= m - 1;
                    atomicOr(&s_bits[r][t][w], mybit);
                }
            }
        }
    }
    BARG();

    // ---- build sorted encoder active list for t=0 (warp scan, no atomics) ----
    if (g < 32) {
        uint32_t w = s_bits[r][0][g];
        int tot, p = wscan_excl(__popc(w), g, tot);
        uint16_t* dst = s_l1[0][r];
        while (w) {
            int b = __ffs(w) - 1; w &= w - 1;
            dst[p++] = (uint16_t)((g << 5) | b);
        }
        if (g == 31) s_cntA[0][r] = tot;
    }
    BARG();

    float v1[4] = {0,0,0,0}, i1[4] = {0,0,0,0};
    float v2[4] = {0,0,0,0}, i2[4] = {0,0,0,0};
    float v3[4] = {0,0,0,0}, i3[4] = {0,0,0,0};
    float q[4]  = {0,0,0,0};
    unsigned long long c01, c23;   // W3[z1] partial, carried phase2 -> phase3
    int zpack;                     // bits 0-3: z1, bits 4-7: z2

    // readout coefficients: coef_t = 0.9^(23-t) - 0.8^(23-t)
    float c9 = 1.0f, c8 = 1.0f;
#pragma unroll
    for (int i = 0; i < T_ - 1; i++) { c9 *= 0.9f; c8 *= 0.8f; }

    const char* W1b = (const char*)g_W1T + (size_t)j0 * 4;
    const char* W2b = (const char*)g_W2T + (size_t)j0 * 4;
    const char* W3b = (const char*)g_W3T + (size_t)j0 * 4;

#pragma unroll 1
    for (int t = 0; t < T_; t++) {
        const int ep = t & 1;
        // ================= phase 1: layer 1 =================
        {
            float4 bv = *(const float4*)(b1 + j0);
            unsigned long long a01 = pk2(bv.x, bv.y), a23 = pk2(bv.z, bv.w);
            unsigned long long d01 = pk2(0.f, 0.f),   d23 = pk2(0.f, 0.f);
            const uint16_t* lst = s_l1[ep][r];
            const int n = s_cntA[ep][r];
            int e = 0;
            for (; e + 4 <= n; e += 4) {
                ushort4 o = *(const ushort4*)(lst + e);
                ulonglong2 w0 = *(const ulonglong2*)(W1b + ((uint32_t)o.x << 10));
                ulonglong2 w1 = *(const ulonglong2*)(W1b + ((uint32_t)o.y << 10));
                ulonglong2 w2 = *(const ulonglong2*)(W1b + ((uint32_t)o.z << 10));
                ulonglong2 w3 = *(const ulonglong2*)(W1b + ((uint32_t)o.w << 10));
                addx2(a01, w0.x); addx2(a23, w0.y);
                addx2(d01, w1.x); addx2(d23, w1.y);
                addx2(a01, w2.x); addx2(a23, w2.y);
                addx2(d01, w3.x); addx2(d23, w3.y);
            }
            for (; e < n; e++) {
                ulonglong2 w = *(const ulonglong2*)(W1b + ((uint32_t)lst[e] << 10));
                addx2(a01, w.x); addx2(a23, w.y);
            }
            addx2(a01, d01); addx2(a23, d23);
            float a[4]; upk2(a01, a[0], a[1]); upk2(a23, a[2], a[3]);
            int zb = 0;
#pragma unroll
            for (int u = 0; u < 4; u++) {
                float vd = v1[u] + 0.1f * (i1[u] - v1[u]);
                i1[u] = i1[u] * 0.8f + a[u];
                bool z = vd > 0.23f;
                v1[u] = z ? 0.0f : vd;
                zb |= (z ? (1 << u) : 0);
            }
            zpack = zb;
            // ballot append to z1 list (1 atomic per warp)
            int tot, excl = wscan_excl(__popc(zb), lane, tot);
            int base = 0;
            if (lane == 31 && tot) base = atomicAdd(&s_cnt1[r], tot);
            base = __shfl_sync(0xffffffffu, base, 31) + excl;
            uint32_t* dl = s_lz1[r];
#pragma unroll
            for (int u = 0; u < 4; u++)
                if ((zb >> u) & 1) dl[base++] = (uint32_t)((j0 + u) << 10);
            if (g == 0) s_cnt2[r] = 0;    // last read phase3(t-1)
        }
        BARG();

        // ========== phase 2: dual gather W2[z1] + W3[z1]; next enc list ==========
        {
            float4 bv2 = *(const float4*)(b2 + j0);
            float4 bv3 = *(const float4*)(b3 + j0);
            unsigned long long a01 = pk2(bv2.x, bv2.y), a23 = pk2(bv2.z, bv2.w);
            c01 = pk2(bv3.x, bv3.y); c23 = pk2(bv3.z, bv3.w);
            const uint32_t* lz = s_lz1[r];
            const int n1 = s_cnt1[r];
            int e = 0;
            for (; e + 2 <= n1; e += 2) {
                uint2 o = *(const uint2*)(lz + e);
                ulonglong2 wa0 = *(const ulonglong2*)(W2b + o.x);
                ulonglong2 wc0 = *(const ulonglong2*)(W3b + o.x);
                ulonglong2 wa1 = *(const ulonglong2*)(W2b + o.y);
                ulonglong2 wc1 = *(const ulonglong2*)(W3b + o.y);
                addx2(a01, wa0.x); addx2(a23, wa0.y);
                addx2(c01, wc0.x); addx2(c23, wc0.y);
                addx2(a01, wa1.x); addx2(a23, wa1.y);
                addx2(c01, wc1.x); addx2(c23, wc1.y);
            }
            if (e < n1) {
                uint32_t o = lz[e];
                ulonglong2 wa = *(const ulonglong2*)(W2b + o);
                ulonglong2 wc = *(const ulonglong2*)(W3b + o);
                addx2(a01, wa.x); addx2(a23, wa.y);
                addx2(c01, wc.x); addx2(c23, wc.y);
            }
            float a[4]; upk2(a01, a[0], a[1]); upk2(a23, a[2], a[3]);
            int zb = 0;
#pragma unroll
            for (int u = 0; u < 4; u++) {
                float vd = v2[u] + 0.1f * (i2[u] - v2[u]);
                i2[u] = i2[u] * 0.8f + a[u];
                bool z = vd > 0.23f;
                v2[u] = z ? 0.0f : vd;
                zb |= (z ? (1 << u) : 0);
            }
            zpack |= zb << 4;
            int tot, excl = wscan_excl(__popc(zb), lane, tot);
            int base = 0;
            if (lane == 31 && tot) base = atomicAdd(&s_cnt2[r], tot);
            base = __shfl_sync(0xffffffffu, base, 31) + excl;
            uint32_t* dl = s_lz2[r];
#pragma unroll
            for (int u = 0; u < 4; u++)
                if ((zb >> u) & 1) dl[base++] = (uint32_t)((j0 + u) << 10);

            // build sorted encoder list for t+1 (warp 2r only, no atomics)
            if (t < T_ - 1 && g < 32) {
                uint32_t w = s_bits[r][t + 1][g];
                int tt, p = wscan_excl(__popc(w), g, tt);
                uint16_t* dst = s_l1[ep ^ 1][r];
                while (w) {
                    int b = __ffs(w) - 1; w &= w - 1;
                    dst[p++] = (uint16_t)((g << 5) | b);
                }
                if (g == 31) s_cntA[ep ^ 1][r] = tt;
            }
        }
        BARG();

        // ===== phase 3: gather W3[z2] into carried chains; fold readout; prefetch W1 =====
        {
            unsigned long long d01 = pk2(0.f, 0.f), d23 = pk2(0.f, 0.f);
            gatherN(W3b, s_lz2[r], s_cnt2[r], c01, c23, d01, d23);
            addx2(c01, d01); addx2(c23, d23);
            float a[4]; upk2(c01, a[0], a[1]); upk2(c23, a[2], a[3]);
            float coef = c9 - c8;
            c9 *= (1.0f / 0.9f);
            c8 *= 1.25f;
            const int zb = zpack;
#pragma unroll
            for (int u = 0; u < 4; u++) {
                float vd = v3[u] + 0.1f * (i3[u] - v3[u]);
                i3[u] = i3[u] * 0.8f + a[u];
                bool z = vd > 0.23f;
                v3[u] = z ? 0.0f : vd;
                float o3 = (z ? 1.0f : 0.0f)
                         + (float)((zb >> u) & 1) + (float)((zb >> (u + 4)) & 1);
                q[u] = fmaf(coef, o3, q[u]);
            }
            if (g == 0) s_cnt1[r] = 0;    // last read this step's phase 2
            // prefetch next step's W1 slices into L1
            if (t < T_ - 1) {
                const int nn = s_cntA[ep ^ 1][r];
                const uint16_t* ln = s_l1[ep ^ 1][r];
                for (int e = 0; e < nn; e++)
                    pref1(W1b + ((uint32_t)ln[e] << 10));
            }
        }
        BARG();
    }

    // ---- final readout: out[b][c] = sum_k q_k * Wli[c][k] ----
    const int wig = (tid >> 5) & 1;
#pragma unroll
    for (int c = 0; c < C_; c++) {
        float4 w = *(const float4*)(Wli + c * H_ + j0);
        float s = q[0] * w.x + q[1] * w.y + q[2] * w.z + q[3] * w.w;
#pragma unroll
        for (int off = 16; off; off >>= 1)
            s += __shfl_xor_sync(0xffffffffu, s, off);
        if (lane == 0) s_part[r][wig][c] = s;
    }
    BARG();
    if (g < C_) out[(size_t)row * C_ + g] = s_part[r][0][g] + s_part[r][1][g];
}

// ============================================================
extern "C" void kernel_launch(void* const* d_in, const int* in_sizes, int n_in,
                              void* d_out, int out_size) {
    (void)in_sizes; (void)n_in; (void)out_size;
    const float* x   = (const float*)d_in[0];
    const float* W1  = (const float*)d_in[1];
    const float* b1  = (const float*)d_in[2];
    const float* W2  = (const float*)d_in[3];
    const float* b2  = (const float*)d_in[4];
    const float* W3  = (const float*)d_in[5];
    const float* b3  = (const float*)d_in[6];
    const float* Wli = (const float*)d_in[7];
    float* out = (float*)d_out;

    transpose_all<<<dim3(F_ / 32, H_ / 32, 3), dim3(32, 8)>>>(W1, W2, W3);
    snn_kernel<<<B_ / RPB, 256>>>(x, b1, b2, b3, Wli, out);
}

// round 5
// speedup vs baseline: 1.0302x; 1.0302x over previous
#include <cuda_runtime.h>
#include <stdint.h>

#define B_   4096
#define F_   1024
#define H_   256
#define C_   10
#define T_   24
#define RPB  4

// ---- transposed weights (device globals; no allocation) ----
__device__ __align__(16) float g_W1T[F_ * H_];   // [f][j]
__device__ __align__(16) float g_W2T[H_ * H_];   // [k][j]
__device__ __align__(16) float g_W3T[H_ * H_];   // [k][j]

// ---- packed f32x2 helpers (Blackwell) ----
__device__ __forceinline__ unsigned long long pk2(float lo, float hi) {
    unsigned long long r;
    asm("mov.b64 %0, {%1, %2};" : "=l"(r) : "f"(lo), "f"(hi));
    return r;
}
__device__ __forceinline__ void upk2(unsigned long long v, float& lo, float& hi) {
    asm("mov.b64 {%0, %1}, %2;" : "=f"(lo), "=f"(hi) : "l"(v));
}
__device__ __forceinline__ void addx2(unsigned long long& a, unsigned long long b) {
    asm("add.rn.f32x2 %0, %1, %2;" : "=l"(a) : "l"(a), "l"(b));
}
__device__ __forceinline__ void pref1(const char* p) {
    asm volatile("prefetch.global.L1 [%0];" :: "l"(p));
}

// per-row-group barrier (64 threads, ids 1..RPB)
#define BARG() asm volatile("bar.sync %0, 64;" :: "r"(barid) : "memory")

// warp exclusive scan; also returns warp total
__device__ __forceinline__ int wscan_excl(int v, int lane, int& total) {
    int inc = v;
#pragma unroll
    for (int off = 1; off < 32; off <<= 1) {
        int y = __shfl_up_sync(0xffffffffu, inc, off);
        if (lane >= off) inc += y;
    }
    total = __shfl_sync(0xffffffffu, inc, 31);
    return inc - v;
}

// ============================================================
// Tiled transpose of W1/W2/W3 into device globals.
// ============================================================
__global__ void __launch_bounds__(256) transpose_all(
    const float* __restrict__ W1, const float* __restrict__ W2,
    const float* __restrict__ W3) {
    __shared__ float tile[32][33];
    const int zi = blockIdx.z;
    const float* src = (zi == 0) ? W1 : ((zi == 1) ? W2 : W3);
    float* dst = (zi == 0) ? g_W1T : ((zi == 1) ? g_W2T : g_W3T);
    const int C = (zi == 0) ? F_ : H_;
    const int R = H_;
    if ((int)(blockIdx.x * 32) >= C) return;

    const int x = blockIdx.x * 32 + threadIdx.x;
    const int y0 = blockIdx.y * 32;
#pragma unroll
    for (int dy = threadIdx.y; dy < 32; dy += 8)
        tile[dy][threadIdx.x] = src[(size_t)(y0 + dy) * C + x];
    __syncthreads();
    const int x2 = y0 + threadIdx.x;
#pragma unroll
    for (int dy = threadIdx.y; dy < 32; dy += 8)
        dst[(size_t)(blockIdx.x * 32 + dy) * R + x2] = tile[threadIdx.x][dy];
}

// ============================================================
// gather over prescaled byte offsets, 4 accumulator chains, unroll 4
// ============================================================
__device__ __forceinline__ void gatherN(const char* __restrict__ wb,
                                        const uint32_t* __restrict__ lst, int n,
                                        unsigned long long& a01, unsigned long long& a23,
                                        unsigned long long& b01, unsigned long long& b23) {
    int e = 0;
    for (; e + 4 <= n; e += 4) {
        uint4 o = *(const uint4*)(lst + e);
        ulonglong2 w0 = *(const ulonglong2*)(wb + o.x);
        ulonglong2 w1 = *(const ulonglong2*)(wb + o.y);
        ulonglong2 w2 = *(const ulonglong2*)(wb + o.z);
        ulonglong2 w3 = *(const ulonglong2*)(wb + o.w);
        addx2(a01, w0.x); addx2(a23, w0.y);
        addx2(b01, w1.x); addx2(b23, w1.y);
        addx2(a01, w2.x); addx2(a23, w2.y);
        addx2(b01, w3.x); addx2(b23, w3.y);
    }
    for (; e < n; e++) {
        ulonglong2 w = *(const ulonglong2*)(wb + lst[e]);
        addx2(a01, w.x); addx2(a23, w.y);
    }
}

// ============================================================
// Main fused kernel: encoder + 24-step SNN + folded linear readout.
// 256 threads = RPB(4) independent 64-thread row groups (named barriers).
// Thread g owns hidden units [4g,4g+3]; LIF state in registers.
// Phase 1: W1 gather (cooperatively L1-prefetched one step ahead) -> z1.
// Phase 2: dual gather W2[z1] + W3[z1]; z2 list; build next enc list.
// Phase 3: gather W3[z2]; fold readout; cooperative line prefetch of W1.
// ============================================================
__global__ void __launch_bounds__(256, 4)
snn_kernel(const float* __restrict__ x,
           const float* __restrict__ b1, const float* __restrict__ b2,
           const float* __restrict__ b3, const float* __restrict__ Wli,
           float* __restrict__ out) {
    __shared__ uint32_t s_bits[RPB][T_][32];                 // 12 KB
    __shared__ __align__(16) uint16_t s_l1[2][RPB][512];     // 8 KB (sorted enc lists)
    __shared__ __align__(16) uint32_t s_lz1[RPB][H_];        // 4 KB (z1 byte offsets)
    __shared__ __align__(16) uint32_t s_lz2[RPB][H_];        // 4 KB (z2 byte offsets)
    __shared__ int s_cntA[2][RPB];
    __shared__ int s_cnt1[RPB];
    __shared__ int s_cnt2[RPB];
    __shared__ float s_part[RPB][2][C_];

    const int tid = threadIdx.x;
    const int r = tid >> 6;
    const int g = tid & 63;
    const int lane = tid & 31;
    const int j0 = g * 4;
    const int barid = r + 1;
    const int row = blockIdx.x * RPB + r;
    const float* xrow = x + (size_t)row * F_;

    // ---- zero this row's bitmaps & counters ----
    for (int i = g; i < T_ * 32; i += 64) ((uint32_t*)s_bits[r])[i] = 0;
    if (g == 0) { s_cnt1[r] = 0; s_cnt2[r] = 0; }
    BARG();

    // ---- fused encoder -> scatter spikes into per-step bitmaps ----
    {
        const uint32_t mybit = 1u << (g & 31);
        const int wbase = g >> 5;
#pragma unroll 1
        for (int m0 = 0; m0 < 16; m0 += 4) {
            float xv[4], vv[4];
            uint32_t mk[4];
#pragma unroll
            for (int j = 0; j < 4; j++) {
                xv[j] = xrow[g + 64 * (m0 + j)];
                vv[j] = 0.0f; mk[j] = 0u;
            }
#pragma unroll
            for (int t = 0; t < T_; t++) {
#pragma unroll
                for (int j = 0; j < 4; j++) {
                    vv[j] = vv[j] + 0.1f * (xv[j] - vv[j]);
                    if (vv[j] > 1.0f) { mk[j] |= (1u << t); vv[j] = 0.0f; }
                }
            }
#pragma unroll
            for (int j = 0; j < 4; j++) {
                uint32_t m = mk[j];
                const int w = wbase + 2 * (m0 + j);
                while (m) {
                    int t = __ffs(m) - 1; m &= m - 1;
                    atomicOr(&s_bits[r][t][w], mybit);
                }
            }
        }
    }
    BARG();

    // ---- build sorted encoder active list for t=0 (warp scan, no atomics) ----
    if (g < 32) {
        uint32_t w = s_bits[r][0][g];
        int tot, p = wscan_excl(__popc(w), g, tot);
        uint16_t* dst = s_l1[0][r];
        while (w) {
            int b = __ffs(w) - 1; w &= w - 1;
            dst[p++] = (uint16_t)((g << 5) | b);
        }
        if (g == 31) s_cntA[0][r] = tot;
    }
    BARG();

    float v1[4] = {0,0,0,0}, i1[4] = {0,0,0,0};
    float v2[4] = {0,0,0,0}, i2[4] = {0,0,0,0};
    float v3[4] = {0,0,0,0}, i3[4] = {0,0,0,0};
    float q[4]  = {0,0,0,0};
    unsigned long long c01, c23;   // W3[z1] partial, carried phase2 -> phase3
    int zpack;                     // bits 0-3: z1, bits 4-7: z2

    // readout coefficients: coef_t = 0.9^(23-t) - 0.8^(23-t)
    float c9 = 1.0f, c8 = 1.0f;
#pragma unroll
    for (int i = 0; i < T_ - 1; i++) { c9 *= 0.9f; c8 *= 0.8f; }

    const char* W1b = (const char*)g_W1T + (size_t)j0 * 4;
    const char* W2b = (const char*)g_W2T + (size_t)j0 * 4;
    const char* W3b = (const char*)g_W3T + (size_t)j0 * 4;

#pragma unroll 1
    for (int t = 0; t < T_; t++) {
        const int ep = t & 1;
        // ================= phase 1: layer 1 =================
        {
            float4 bv = *(const float4*)(b1 + j0);
            unsigned long long a01 = pk2(bv.x, bv.y), a23 = pk2(bv.z, bv.w);
            unsigned long long d01 = pk2(0.f, 0.f),   d23 = pk2(0.f, 0.f);
            const uint16_t* lst = s_l1[ep][r];
            const int n = s_cntA[ep][r];
            int e = 0;
            for (; e + 4 <= n; e += 4) {
                ushort4 o = *(const ushort4*)(lst + e);
                ulonglong2 w0 = *(const ulonglong2*)(W1b + ((uint32_t)o.x << 10));
                ulonglong2 w1 = *(const ulonglong2*)(W1b + ((uint32_t)o.y << 10));
                ulonglong2 w2 = *(const ulonglong2*)(W1b + ((uint32_t)o.z << 10));
                ulonglong2 w3 = *(const ulonglong2*)(W1b + ((uint32_t)o.w << 10));
                addx2(a01, w0.x); addx2(a23, w0.y);
                addx2(d01, w1.x); addx2(d23, w1.y);
                addx2(a01, w2.x); addx2(a23, w2.y);
                addx2(d01, w3.x); addx2(d23, w3.y);
            }
            for (; e < n; e++) {
                ulonglong2 w = *(const ulonglong2*)(W1b + ((uint32_t)lst[e] << 10));
                addx2(a01, w.x); addx2(a23, w.y);
            }
            addx2(a01, d01); addx2(a23, d23);
            float a[4]; upk2(a01, a[0], a[1]); upk2(a23, a[2], a[3]);
            int zb = 0;
#pragma unroll
            for (int u = 0; u < 4; u++) {
                float vd = v1[u] + 0.1f * (i1[u] - v1[u]);
                i1[u] = i1[u] * 0.8f + a[u];
                bool z = vd > 0.23f;
                v1[u] = z ? 0.0f : vd;
                zb |= (z ? (1 << u) : 0);
            }
            zpack = zb;
            // ballot append to z1 list (1 atomic per warp)
            int tot, excl = wscan_excl(__popc(zb), lane, tot);
            int base = 0;
            if (lane == 31 && tot) base = atomicAdd(&s_cnt1[r], tot);
            base = __shfl_sync(0xffffffffu, base, 31) + excl;
            uint32_t* dl = s_lz1[r];
#pragma unroll
            for (int u = 0; u < 4; u++)
                if ((zb >> u) & 1) dl[base++] = (uint32_t)((j0 + u) << 10);
            if (g == 0) s_cnt2[r] = 0;    // last read phase3(t-1)
        }
        BARG();

        // ========== phase 2: dual gather W2[z1] + W3[z1]; next enc list ==========
        {
            float4 bv2 = *(const float4*)(b2 + j0);
            float4 bv3 = *(const float4*)(b3 + j0);
            unsigned long long a01 = pk2(bv2.x, bv2.y), a23 = pk2(bv2.z, bv2.w);
            c01 = pk2(bv3.x, bv3.y); c23 = pk2(bv3.z, bv3.w);
            const uint32_t* lz = s_lz1[r];
            const int n1 = s_cnt1[r];
            int e = 0;
            for (; e + 2 <= n1; e += 2) {
                uint2 o = *(const uint2*)(lz + e);
                ulonglong2 wa0 = *(const ulonglong2*)(W2b + o.x);
                ulonglong2 wc0 = *(const ulonglong2*)(W3b + o.x);
                ulonglong2 wa1 = *(const ulonglong2*)(W2b + o.y);
                ulonglong2 wc1 = *(const ulonglong2*)(W3b + o.y);
                addx2(a01, wa0.x); addx2(a23, wa0.y);
                addx2(c01, wc0.x); addx2(c23, wc0.y);
                addx2(a01, wa1.x); addx2(a23, wa1.y);
                addx2(c01, wc1.x); addx2(c23, wc1.y);
            }
            if (e < n1) {
                uint32_t o = lz[e];
                ulonglong2 wa = *(const ulonglong2*)(W2b + o);
                ulonglong2 wc = *(const ulonglong2*)(W3b + o);
                addx2(a01, wa.x); addx2(a23, wa.y);
                addx2(c01, wc.x); addx2(c23, wc.y);
            }
            float a[4]; upk2(a01, a[0], a[1]); upk2(a23, a[2], a[3]);
            int zb = 0;
#pragma unroll
            for (int u = 0; u < 4; u++) {
                float vd = v2[u] + 0.1f * (i2[u] - v2[u]);
                i2[u] = i2[u] * 0.8f + a[u];
                bool z = vd > 0.23f;
                v2[u] = z ? 0.0f : vd;
                zb |= (z ? (1 << u) : 0);
            }
            zpack |= zb << 4;
            int tot, excl = wscan_excl(__popc(zb), lane, tot);
            int base = 0;
            if (lane == 31 && tot) base = atomicAdd(&s_cnt2[r], tot);
            base = __shfl_sync(0xffffffffu, base, 31) + excl;
            uint32_t* dl = s_lz2[r];
#pragma unroll
            for (int u = 0; u < 4; u++)
                if ((zb >> u) & 1) dl[base++] = (uint32_t)((j0 + u) << 10);

            // build sorted encoder list for t+1 (warp 2r only, no atomics)
            if (t < T_ - 1 && g < 32) {
                uint32_t w = s_bits[r][t + 1][g];
                int tt, p = wscan_excl(__popc(w), g, tt);
                uint16_t* dst = s_l1[ep ^ 1][r];
                while (w) {
                    int b = __ffs(w) - 1; w &= w - 1;
                    dst[p++] = (uint16_t)((g << 5) | b);
                }
                if (g == 31) s_cntA[ep ^ 1][r] = tt;
            }
        }
        BARG();

        // ===== phase 3: gather W3[z2] into carried chains; fold readout;
        //       cooperative 128B-line prefetch of next step's W1 columns =====
        {
            unsigned long long d01 = pk2(0.f, 0.f), d23 = pk2(0.f, 0.f);
            gatherN(W3b, s_lz2[r], s_cnt2[r], c01, c23, d01, d23);
            addx2(c01, d01); addx2(c23, d23);
            float a[4]; upk2(c01, a[0], a[1]); upk2(c23, a[2], a[3]);
            float coef = c9 - c8;
            c9 *= (1.0f / 0.9f);
            c8 *= 1.25f;
            const int zb = zpack;
#pragma unroll
            for (int u = 0; u < 4; u++) {
                float vd = v3[u] + 0.1f * (i3[u] - v3[u]);
                i3[u] = i3[u] * 0.8f + a[u];
                bool z = vd > 0.23f;
                v3[u] = z ? 0.0f : vd;
                float o3 = (z ? 1.0f : 0.0f)
                         + (float)((zb >> u) & 1) + (float)((zb >> (u + 4)) & 1);
                q[u] = fmaf(coef, o3, q[u]);
            }
            if (g == 0) s_cnt1[r] = 0;    // last read this step's phase 2
            // cooperative prefetch: 1 KB column = 8 lines; i enumerates (col, line)
            // pairs across all 64 threads -> ~n/8 prefetches per thread.
            if (t < T_ - 1) {
                const int nn8 = s_cntA[ep ^ 1][r] << 3;
                const uint16_t* ln = s_l1[ep ^ 1][r];
                const char* base = (const char*)g_W1T;
                for (int i = g; i < nn8; i += 64)
                    pref1(base + ((uint32_t)ln[i >> 3] << 10) + ((i & 7) << 7));
            }
        }
        BARG();
    }

    // ---- final readout: out[b][c] = sum_k q_k * Wli[c][k] ----
    const int wig = (tid >> 5) & 1;
#pragma unroll
    for (int c = 0; c < C_; c++) {
        float4 w = *(const float4*)(Wli + c * H_ + j0);
        float s = q[0] * w.x + q[1] * w.y + q[2] * w.z + q[3] * w.w;
#pragma unroll
        for (int off = 16; off; off >>= 1)
            s += __shfl_xor_sync(0xffffffffu, s, off);
        if (lane == 0) s_part[r][wig][c] = s;
    }
    BARG();
    if (g < C_) out[(size_t)row * C_ + g] = s_part[r][0][g] + s_part[r][1][g];
}

// ============================================================
extern "C" void kernel_launch(void* const* d_in, const int* in_sizes, int n_in,
                              void* d_out, int out_size) {
    (void)in_sizes; (void)n_in; (void)out_size;
    const float* x   = (const float*)d_in[0];
    const float* W1  = (const float*)d_in[1];
    const float* b1  = (const float*)d_in[2];
    const float* W2  = (const float*)d_in[3];
    const float* b2  = (const float*)d_in[4];
    const float* W3  = (const float*)d_in[5];
    const float* b3  = (const float*)d_in[6];
    const float* Wli = (const float*)d_in[7];
    float* out = (float*)d_out;

    transpose_all<<<dim3(F_ / 32, H_ / 32, 3), dim3(32, 8)>>>(W1, W2, W3);
    snn_kernel<<<B_ / RPB, 256>>>(x, b1, b2, b3, Wli, out);
}

// round 6
// speedup vs baseline: 1.1832x; 1.1485x over previous
#include <cuda_runtime.h>
#include <stdint.h>

#define B_   4096
#define F_   1024
#define H_   256
#define C_   10
#define T_   24
#define RPB  4

// ---- transposed weights (device globals; no allocation) ----
__device__ __align__(16) float g_W1T[F_ * H_];   // [f][j]
__device__ __align__(16) float g_W2T[H_ * H_];   // [k][j]
__device__ __align__(16) float g_W3T[H_ * H_];   // [k][j]

// ---- packed f32x2 helpers (Blackwell) ----
__device__ __forceinline__ unsigned long long pk2(float lo, float hi) {
    unsigned long long r;
    asm("mov.b64 %0, {%1, %2};" : "=l"(r) : "f"(lo), "f"(hi));
    return r;
}
__device__ __forceinline__ void upk2(unsigned long long v, float& lo, float& hi) {
    asm("mov.b64 {%0, %1}, %2;" : "=f"(lo), "=f"(hi) : "l"(v));
}
__device__ __forceinline__ void addx2(unsigned long long& a, unsigned long long b) {
    asm("add.rn.f32x2 %0, %1, %2;" : "=l"(a) : "l"(a), "l"(b));
}

// per-row-group barrier (64 threads, ids 1..RPB)
#define BARG() asm volatile("bar.sync %0, 64;" :: "r"(barid) : "memory")

// warp exclusive scan; also returns warp total
__device__ __forceinline__ int wscan_excl(int v, int lane, int& total) {
    int inc = v;
#pragma unroll
    for (int off = 1; off < 32; off <<= 1) {
        int y = __shfl_up_sync(0xffffffffu, inc, off);
        if (lane >= off) inc += y;
    }
    total = __shfl_sync(0xffffffffu, inc, 31);
    return inc - v;
}

// ============================================================
// Tiled transpose of W1/W2/W3 into device globals.
// ============================================================
__global__ void __launch_bounds__(256) transpose_all(
    const float* __restrict__ W1, const float* __restrict__ W2,
    const float* __restrict__ W3) {
    __shared__ float tile[32][33];
    const int zi = blockIdx.z;
    const float* src = (zi == 0) ? W1 : ((zi == 1) ? W2 : W3);
    float* dst = (zi == 0) ? g_W1T : ((zi == 1) ? g_W2T : g_W3T);
    const int C = (zi == 0) ? F_ : H_;
    const int R = H_;
    if ((int)(blockIdx.x * 32) >= C) return;

    const int x = blockIdx.x * 32 + threadIdx.x;
    const int y0 = blockIdx.y * 32;
#pragma unroll
    for (int dy = threadIdx.y; dy < 32; dy += 8)
        tile[dy][threadIdx.x] = src[(size_t)(y0 + dy) * C + x];
    __syncthreads();
    const int x2 = y0 + threadIdx.x;
#pragma unroll
    for (int dy = threadIdx.y; dy < 32; dy += 8)
        dst[(size_t)(blockIdx.x * 32 + dy) * R + x2] = tile[threadIdx.x][dy];
}

// ============================================================
// gather: acc += sum of W columns (u16 indices, row stride 1KB)
// 4 accumulator chains, unroll 4
// ============================================================
__device__ __forceinline__ void gather16(const char* __restrict__ wb,
                                         const uint16_t* __restrict__ lst, int n,
                                         unsigned long long& a01, unsigned long long& a23,
                                         unsigned long long& d01, unsigned long long& d23) {
    int e = 0;
    for (; e + 4 <= n; e += 4) {
        ushort4 o = *(const ushort4*)(lst + e);
        ulonglong2 w0 = *(const ulonglong2*)(wb + ((uint32_t)o.x << 10));
        ulonglong2 w1 = *(const ulonglong2*)(wb + ((uint32_t)o.y << 10));
        ulonglong2 w2 = *(const ulonglong2*)(wb + ((uint32_t)o.z << 10));
        ulonglong2 w3 = *(const ulonglong2*)(wb + ((uint32_t)o.w << 10));
        addx2(a01, w0.x); addx2(a23, w0.y);
        addx2(d01, w1.x); addx2(d23, w1.y);
        addx2(a01, w2.x); addx2(a23, w2.y);
        addx2(d01, w3.x); addx2(d23, w3.y);
    }
    for (; e < n; e++) {
        ulonglong2 w = *(const ulonglong2*)(wb + ((uint32_t)lst[e] << 10));
        addx2(a01, w.x); addx2(a23, w.y);
    }
}

// ============================================================
// Main fused kernel: encoder + 23-step SNN (step 23 has zero output
// weight and feeds nothing -> elided) + folded linear readout.
// 256 threads = RPB(4) independent 64-thread row groups (named barriers).
// Thread g owns hidden units [4g,4g+3]; LIF state in registers.
//
// 2 phases/step:
//  A: gather W3[L_{t-1}] (finish i3 of step t-1), layer-3 decay -> z3;
//     gather W1[enc_t], layer-1 LIF -> z1; append z1 to L_t.
//  B: gather W2[z1_t], layer-2 LIF -> z2; append z2 to L_t;
//     readout fold (o3 = z1+z2+z3, all local); build enc list for t+1.
// ============================================================
__global__ void __launch_bounds__(256, 4)
snn_kernel(const float* __restrict__ x,
           const float* __restrict__ b1, const float* __restrict__ b2,
           const float* __restrict__ b3, const float* __restrict__ Wli,
           float* __restrict__ out) {
    __shared__ uint32_t s_bits[RPB][T_][32];                 // 12 KB
    __shared__ __align__(16) uint16_t s_l1[2][RPB][512];     // 8 KB (sorted enc lists)
    __shared__ __align__(16) uint16_t s_lL[2][RPB][512];     // 8 KB (o2 lists: z1 then z2)
    __shared__ int s_cntA[2][RPB];                           // enc counts
    __shared__ int s_cn1[2][RPB];                            // z1 counts
    __shared__ int s_cn2[2][RPB];                            // z2 counts
    __shared__ float s_part[RPB][2][C_];

    const int tid = threadIdx.x;
    const int r = tid >> 6;
    const int g = tid & 63;
    const int lane = tid & 31;
    const int j0 = g * 4;
    const int barid = r + 1;
    const int row = blockIdx.x * RPB + r;
    const float* xrow = x + (size_t)row * F_;

    // ---- zero this row's bitmaps & parity-0 counters ----
    for (int i = g; i < T_ * 32; i += 64) ((uint32_t*)s_bits[r])[i] = 0;
    if (g == 0) { s_cn1[0][r] = 0; s_cn2[0][r] = 0; }
    BARG();

    // ---- fused encoder -> scatter spikes into per-step bitmaps ----
    {
        const uint32_t mybit = 1u << (g & 31);
        const int wbase = g >> 5;
#pragma unroll 1
        for (int m0 = 0; m0 < 16; m0 += 4) {
            float xv[4], vv[4];
            uint32_t mk[4];
#pragma unroll
            for (int j = 0; j < 4; j++) {
                xv[j] = xrow[g + 64 * (m0 + j)];
                vv[j] = 0.0f; mk[j] = 0u;
            }
#pragma unroll
            for (int t = 0; t < T_; t++) {
#pragma unroll
                for (int j = 0; j < 4; j++) {
                    vv[j] = vv[j] + 0.1f * (xv[j] - vv[j]);
                    if (vv[j] > 1.0f) { mk[j] |= (1u << t); vv[j] = 0.0f; }
                }
            }
#pragma unroll
            for (int j = 0; j < 4; j++) {
                uint32_t m = mk[j];
                const int w = wbase + 2 * (m0 + j);
                while (m) {
                    int t = __ffs(m) - 1; m &= m - 1;
                    atomicOr(&s_bits[r][t][w], mybit);
                }
            }
        }
    }
    BARG();

    // ---- build sorted encoder active list for t=0 (warp0 scan, no atomics) ----
    if (g < 32) {
        uint32_t w = s_bits[r][0][g];
        int tot, p = wscan_excl(__popc(w), g, tot);
        uint16_t* dst = s_l1[0][r];
        while (w) {
            int b = __ffs(w) - 1; w &= w - 1;
            dst[p++] = (uint16_t)((g << 5) | b);
        }
        if (g == 31) s_cntA[0][r] = tot;
    }
    BARG();

    float v1[4] = {0,0,0,0}, i1[4] = {0,0,0,0};
    float v2[4] = {0,0,0,0}, i2[4] = {0,0,0,0};
    float v3[4] = {0,0,0,0}, i3[4] = {0,0,0,0};
    float q[4]  = {0,0,0,0};
    int z13;                      // bits 0-3: z1, bits 8-11: z3

    // readout coefficients: coef_t = 0.9^(23-t) - 0.8^(23-t)
    float c9 = 1.0f, c8 = 1.0f;
#pragma unroll
    for (int i = 0; i < T_ - 1; i++) { c9 *= 0.9f; c8 *= 0.8f; }

    const char* W1b = (const char*)g_W1T + (size_t)j0 * 4;
    const char* W2b = (const char*)g_W2T + (size_t)j0 * 4;
    const char* W3b = (const char*)g_W3T + (size_t)j0 * 4;

#pragma unroll 1
    for (int t = 0; t < T_ - 1; t++) {      // step 23 elided (coef 0, feeds nothing)
        const int p = t & 1;

        // ============ phase A ============
        {
            // --- finish layer-3 input of step t-1: i3 = 0.8*i3 + (o2 @ W3 + b3) ---
            if (t > 0) {
                float4 bv3 = *(const float4*)(b3 + j0);
                unsigned long long c01 = pk2(bv3.x, bv3.y), c23 = pk2(bv3.z, bv3.w);
                unsigned long long e01 = pk2(0.f, 0.f),    e23 = pk2(0.f, 0.f);
                const int nL = s_cn1[p ^ 1][r] + s_cn2[p ^ 1][r];
                gather16(W3b, s_lL[p ^ 1][r], nL, c01, c23, e01, e23);
                addx2(c01, e01); addx2(c23, e23);
                float c[4]; upk2(c01, c[0], c[1]); upk2(c23, c[2], c[3]);
#pragma unroll
                for (int u = 0; u < 4; u++) i3[u] = i3[u] * 0.8f + c[u];
            }
            // --- layer-3 decay & spike (z3_t) ---
            int z3b = 0;
#pragma unroll
            for (int u = 0; u < 4; u++) {
                float vd = v3[u] + 0.1f * (i3[u] - v3[u]);
                bool z = vd > 0.23f;
                v3[u] = z ? 0.0f : vd;
                z3b |= (z ? (1 << u) : 0);
            }

            // --- layer 1: gather W1[enc_t] ---
            float4 bv = *(const float4*)(b1 + j0);
            unsigned long long a01 = pk2(bv.x, bv.y), a23 = pk2(bv.z, bv.w);
            unsigned long long d01 = pk2(0.f, 0.f),   d23 = pk2(0.f, 0.f);
            gather16(W1b, s_l1[p][r], s_cntA[p][r], a01, a23, d01, d23);
            addx2(a01, d01); addx2(a23, d23);
            float a[4]; upk2(a01, a[0], a[1]); upk2(a23, a[2], a[3]);
            int z1b = 0;
#pragma unroll
            for (int u = 0; u < 4; u++) {
                float vd = v1[u] + 0.1f * (i1[u] - v1[u]);
                i1[u] = i1[u] * 0.8f + a[u];
                bool z = vd > 0.23f;
                v1[u] = z ? 0.0f : vd;
                z1b |= (z ? (1 << u) : 0);
            }
            z13 = z1b | (z3b << 8);
            // append z1 offsets to L_t (1 atomic per warp)
            int tot, excl = wscan_excl(__popc(z1b), lane, tot);
            int base = 0;
            if (lane == 31 && tot) base = atomicAdd(&s_cn1[p][r], tot);
            base = __shfl_sync(0xffffffffu, base, 31) + excl;
            uint16_t* dl = s_lL[p][r];
#pragma unroll
            for (int u = 0; u < 4; u++)
                if ((z1b >> u) & 1) dl[base++] = (uint16_t)(j0 + u);
        }
        BARG();

        // ============ phase B ============
        {
            // --- layer 2: gather W2[z1_t] ---
            float4 bv = *(const float4*)(b2 + j0);
            unsigned long long a01 = pk2(bv.x, bv.y), a23 = pk2(bv.z, bv.w);
            unsigned long long d01 = pk2(0.f, 0.f),   d23 = pk2(0.f, 0.f);
            const int n1 = s_cn1[p][r];
            gather16(W2b, s_lL[p][r], n1, a01, a23, d01, d23);
            addx2(a01, d01); addx2(a23, d23);
            float a[4]; upk2(a01, a[0], a[1]); upk2(a23, a[2], a[3]);
            int z2b = 0;
#pragma unroll
            for (int u = 0; u < 4; u++) {
                float vd = v2[u] + 0.1f * (i2[u] - v2[u]);
                i2[u] = i2[u] * 0.8f + a[u];
                bool z = vd > 0.23f;
                v2[u] = z ? 0.0f : vd;
                z2b |= (z ? (1 << u) : 0);
            }
            // append z2 offsets to L_t after the z1 block
            int tot, excl = wscan_excl(__popc(z2b), lane, tot);
            int base = 0;
            if (lane == 31 && tot) base = atomicAdd(&s_cn2[p][r], tot);
            base = __shfl_sync(0xffffffffu, base, 31) + excl + n1;
            uint16_t* dl = s_lL[p][r];
#pragma unroll
            for (int u = 0; u < 4; u++)
                if ((z2b >> u) & 1) dl[base++] = (uint16_t)(j0 + u);

            // --- readout fold: o3 = z1 + z2 + z3, all thread-local ---
            float coef = c9 - c8;
            c9 *= (1.0f / 0.9f);
            c8 *= 1.25f;
            const int zz = z13;
#pragma unroll
            for (int u = 0; u < 4; u++) {
                float o3 = (float)((zz >> u) & 1) + (float)((zz >> (u + 8)) & 1)
                         + (float)((z2b >> u) & 1);
                q[u] = fmaf(coef, o3, q[u]);
            }

            // zero parity p^1 counters (last read in A(t), next written A(t+1))
            if (g == 0) { s_cn1[p ^ 1][r] = 0; s_cn2[p ^ 1][r] = 0; }

            // build sorted encoder list for t+1 (warp1 scan, no atomics)
            if (t < T_ - 2 && g >= 32) {
                const int l2 = g - 32;
                uint32_t w = s_bits[r][t + 1][l2];
                int tt, pp = wscan_excl(__popc(w), l2, tt);
                uint16_t* dst = s_l1[p ^ 1][r];
                while (w) {
                    int b = __ffs(w) - 1; w &= w - 1;
                    dst[pp++] = (uint16_t)((l2 << 5) | b);
                }
                if (l2 == 31) s_cntA[p ^ 1][r] = tt;
            }
        }
        BARG();
    }

    // ---- final readout: out[b][c] = sum_k q_k * Wli[c][k] ----
    const int wig = (tid >> 5) & 1;
#pragma unroll
    for (int c = 0; c < C_; c++) {
        float4 w = *(const float4*)(Wli + c * H_ + j0);
        float s = q[0] * w.x + q[1] * w.y + q[2] * w.z + q[3] * w.w;
#pragma unroll
        for (int off = 16; off; off >>= 1)
            s += __shfl_xor_sync(0xffffffffu, s, off);
        if (lane == 0) s_part[r][wig][c] = s;
    }
    BARG();
    if (g < C_) out[(size_t)row * C_ + g] = s_part[r][0][g] + s_part[r][1][g];
}

// ============================================================
extern "C" void kernel_launch(void* const* d_in, const int* in_sizes, int n_in,
                              void* d_out, int out_size) {
    (void)in_sizes; (void)n_in; (void)out_size;
    const float* x   = (const float*)d_in[0];
    const float* W1  = (const float*)d_in[1];
    const float* b1  = (const float*)d_in[2];
    const float* W2  = (const float*)d_in[3];
    const float* b2  = (const float*)d_in[4];
    const float* W3  = (const float*)d_in[5];
    const float* b3  = (const float*)d_in[6];
    const float* Wli = (const float*)d_in[7];
    float* out = (float*)d_out;

    transpose_all<<<dim3(F_ / 32, H_ / 32, 3), dim3(32, 8)>>>(W1, W2, W3);
    snn_kernel<<<B_ / RPB, 256>>>(x, b1, b2, b3, Wli, out);
}

// round 7
// speedup vs baseline: 1.3899x; 1.1747x over previous
#include <cuda_runtime.h>
#include <stdint.h>

#define B_   4096
#define F_   1024
#define H_   256
#define C_   10
#define T_   24
#define RPB  4

// ---- transposed weights (device globals; no allocation) ----
__device__ __align__(16) float g_W1T[F_ * H_];   // [f][j]
__device__ __align__(16) float g_W2T[H_ * H_];   // [k][j]
__device__ __align__(16) float g_W3T[H_ * H_];   // [k][j]

// ---- packed f32x2 helpers (Blackwell) ----
__device__ __forceinline__ unsigned long long pk2(float lo, float hi) {
    unsigned long long r;
    asm("mov.b64 %0, {%1, %2};" : "=l"(r) : "f"(lo), "f"(hi));
    return r;
}
__device__ __forceinline__ void upk2(unsigned long long v, float& lo, float& hi) {
    asm("mov.b64 {%0, %1}, %2;" : "=f"(lo), "=f"(hi) : "l"(v));
}
__device__ __forceinline__ void addx2(unsigned long long& a, unsigned long long b) {
    asm("add.rn.f32x2 %0, %1, %2;" : "=l"(a) : "l"(a), "l"(b));
}

// per-row-group barrier (64 threads, ids 1..RPB)
#define BARG() asm volatile("bar.sync %0, 64;" :: "r"(barid) : "memory")

// ============================================================
// Tiled transpose of W1/W2/W3 into device globals.
// ============================================================
__global__ void __launch_bounds__(256) transpose_all(
    const float* __restrict__ W1, const float* __restrict__ W2,
    const float* __restrict__ W3) {
    __shared__ float tile[32][33];
    const int zi = blockIdx.z;
    const float* src = (zi == 0) ? W1 : ((zi == 1) ? W2 : W3);
    float* dst = (zi == 0) ? g_W1T : ((zi == 1) ? g_W2T : g_W3T);
    const int C = (zi == 0) ? F_ : H_;
    const int R = H_;
    if ((int)(blockIdx.x * 32) >= C) return;

    const int x = blockIdx.x * 32 + threadIdx.x;
    const int y0 = blockIdx.y * 32;
#pragma unroll
    for (int dy = threadIdx.y; dy < 32; dy += 8)
        tile[dy][threadIdx.x] = src[(size_t)(y0 + dy) * C + x];
    __syncthreads();
    const int x2 = y0 + threadIdx.x;
#pragma unroll
    for (int dy = threadIdx.y; dy < 32; dy += 8)
        dst[(size_t)(blockIdx.x * 32 + dy) * R + x2] = tile[threadIdx.x][dy];
}

// ============================================================
// gather over prescaled byte offsets, 4 accumulator chains, unroll 4
// ============================================================
__device__ __forceinline__ void gatherN(const char* __restrict__ wb,
                                        const uint32_t* __restrict__ lst, int n,
                                        unsigned long long& a01, unsigned long long& a23,
                                        unsigned long long& b01, unsigned long long& b23) {
    int e = 0;
    for (; e + 4 <= n; e += 4) {
        uint4 o = *(const uint4*)(lst + e);
        ulonglong2 w0 = *(const ulonglong2*)(wb + o.x);
        ulonglong2 w1 = *(const ulonglong2*)(wb + o.y);
        ulonglong2 w2 = *(const ulonglong2*)(wb + o.z);
        ulonglong2 w3 = *(const ulonglong2*)(wb + o.w);
        addx2(a01, w0.x); addx2(a23, w0.y);
        addx2(b01, w1.x); addx2(b23, w1.y);
        addx2(a01, w2.x); addx2(a23, w2.y);
        addx2(b01, w3.x); addx2(b23, w3.y);
    }
    for (; e < n; e++) {
        ulonglong2 w = *(const ulonglong2*)(wb + lst[e]);
        addx2(a01, w.x); addx2(a23, w.y);
    }
}

// ============================================================
// Main fused kernel: encoder + SNN + folded linear readout.
// R3 structure (3 phases, per-item atomic appends), with dead-step
// elision: steps 22 and 23 gathers are dead (step-23 output coef is 0;
// step-22 gathers only update currents read at step 23). Main loop runs
// 22 full steps; step 22 is a local-spike epilogue; step 23 vanishes.
// ============================================================
__global__ void __launch_bounds__(256, 4)
snn_kernel(const float* __restrict__ x,
           const float* __restrict__ b1, const float* __restrict__ b2,
           const float* __restrict__ b3, const float* __restrict__ Wli,
           float* __restrict__ out) {
    __shared__ uint32_t s_bits[RPB][T_][32];                 // 12 KB
    __shared__ __align__(16) uint16_t s_l1[RPB][F_];         // 8 KB
    __shared__ __align__(16) uint32_t s_lh[2][RPB][2 * H_];  // 16 KB (z1 then z2 offsets)
    __shared__ int s_cntA[RPB];
    __shared__ int s_cnt1[2][RPB];
    __shared__ int s_cnt2[2][RPB];
    __shared__ float s_part[RPB][2][C_];

    const int tid = threadIdx.x;
    const int r = tid >> 6;
    const int g = tid & 63;
    const int lane = tid & 31;
    const int j0 = g * 4;
    const int barid = r + 1;
    const int row = blockIdx.x * RPB + r;
    const float* xrow = x + (size_t)row * F_;

    // ---- zero this row's bitmaps & counters ----
    for (int i = g; i < T_ * 32; i += 64) ((uint32_t*)s_bits[r])[i] = 0;
    if (g == 0) {
        s_cntA[r] = 0;
        s_cnt1[0][r] = 0; s_cnt1[1][r] = 0;
        s_cnt2[0][r] = 0; s_cnt2[1][r] = 0;
    }
    BARG();

    // ---- fused encoder -> scatter spikes into per-step bitmaps ----
    {
        const uint32_t mybit = 1u << (g & 31);
        const int wbase = g >> 5;
#pragma unroll 1
        for (int m0 = 0; m0 < 16; m0 += 4) {
            float xv[4], vv[4];
            uint32_t mk[4];
#pragma unroll
            for (int j = 0; j < 4; j++) {
                xv[j] = xrow[g + 64 * (m0 + j)];
                vv[j] = 0.0f; mk[j] = 0u;
            }
#pragma unroll
            for (int t = 0; t < T_; t++) {
#pragma unroll
                for (int j = 0; j < 4; j++) {
                    vv[j] = vv[j] + 0.1f * (xv[j] - vv[j]);
                    if (vv[j] > 1.0f) { mk[j] |= (1u << t); vv[j] = 0.0f; }
                }
            }
#pragma unroll
            for (int j = 0; j < 4; j++) {
                uint32_t m = mk[j];
                const int w = wbase + 2 * (m0 + j);
                while (m) {
                    int t = __ffs(m) - 1; m &= m - 1;
                    atomicOr(&s_bits[r][t][w], mybit);
                }
            }
        }
    }
    BARG();

    // ---- build encoder active list for t=0 ----
    if (g < 32) {
        uint32_t w = s_bits[r][0][g];
        while (w) {
            int b = __ffs(w) - 1; w &= w - 1;
            int p = atomicAdd(&s_cntA[r], 1);
            s_l1[r][p] = (uint16_t)((g << 5) | b);
        }
    }
    BARG();

    float v1[4] = {0,0,0,0}, i1[4] = {0,0,0,0};
    float v2[4] = {0,0,0,0}, i2[4] = {0,0,0,0};
    float v3[4] = {0,0,0,0}, i3[4] = {0,0,0,0};
    float q[4]  = {0,0,0,0};
    float z1f[4], z2f[4];

    // readout coefficients: coef_t = 0.9^(23-t) - 0.8^(23-t)
    float c9 = 1.0f, c8 = 1.0f;
#pragma unroll
    for (int i = 0; i < T_ - 1; i++) { c9 *= 0.9f; c8 *= 0.8f; }

    const char* W1b = (const char*)g_W1T + (size_t)j0 * 4;
    const char* W2b = (const char*)g_W2T + (size_t)j0 * 4;
    const char* W3b = (const char*)g_W3T + (size_t)j0 * 4;

    int par = 0;

#pragma unroll 1
    for (int t = 0; t < T_ - 2; t++) {       // steps 22/23 gathers are dead
        // ================= phase 1: layer 1 =================
        {
            float4 bv = *(const float4*)(b1 + j0);
            unsigned long long a01 = pk2(bv.x, bv.y), a23 = pk2(bv.z, bv.w);
            unsigned long long b01 = pk2(0.f, 0.f),   b23 = pk2(0.f, 0.f);
            const uint16_t* lst = s_l1[r];
            const int n = s_cntA[r];
            int e = 0;
            for (; e + 4 <= n; e += 4) {
                ushort4 o = *(const ushort4*)(lst + e);
                ulonglong2 w0 = *(const ulonglong2*)(W1b + ((uint32_t)o.x << 10));
                ulonglong2 w1 = *(const ulonglong2*)(W1b + ((uint32_t)o.y << 10));
                ulonglong2 w2 = *(const ulonglong2*)(W1b + ((uint32_t)o.z << 10));
                ulonglong2 w3 = *(const ulonglong2*)(W1b + ((uint32_t)o.w << 10));
                addx2(a01, w0.x); addx2(a23, w0.y);
                addx2(b01, w1.x); addx2(b23, w1.y);
                addx2(a01, w2.x); addx2(a23, w2.y);
                addx2(b01, w3.x); addx2(b23, w3.y);
            }
            for (; e < n; e++) {
                ulonglong2 w = *(const ulonglong2*)(W1b + ((uint32_t)lst[e] << 10));
                addx2(a01, w.x); addx2(a23, w.y);
            }
            addx2(a01, b01); addx2(a23, b23);
            float a[4]; upk2(a01, a[0], a[1]); upk2(a23, a[2], a[3]);
            int* cnt = &s_cnt1[par][r];
            uint32_t* dl = s_lh[par][r];
#pragma unroll
            for (int u = 0; u < 4; u++) {
                float vd = v1[u] + 0.1f * (i1[u] - v1[u]);
                i1[u] = i1[u] * 0.8f + a[u];
                bool z = vd > 0.23f;
                v1[u] = z ? 0.0f : vd;
                z1f[u] = z ? 1.0f : 0.0f;
                if (z) { int p = atomicAdd(cnt, 1); dl[p] = (uint32_t)((j0 + u) << 10); }
            }
        }
        BARG();

        // ================= phase 2: layer 2 =================
        {
            if (g == 0) {       // untouched during phase 2
                s_cntA[r] = 0;
                s_cnt1[par ^ 1][r] = 0;
                s_cnt2[par ^ 1][r] = 0;
            }
            float4 bv = *(const float4*)(b2 + j0);
            unsigned long long a01 = pk2(bv.x, bv.y), a23 = pk2(bv.z, bv.w);
            unsigned long long b01 = pk2(0.f, 0.f),   b23 = pk2(0.f, 0.f);
            const int nA = s_cnt1[par][r];          // stable all phase
            gatherN(W2b, s_lh[par][r], nA, a01, a23, b01, b23);
            addx2(a01, b01); addx2(a23, b23);
            float a[4]; upk2(a01, a[0], a[1]); upk2(a23, a[2], a[3]);
            int* cnt = &s_cnt2[par][r];
            uint32_t* dl = s_lh[par][r];
#pragma unroll
            for (int u = 0; u < 4; u++) {
                float vd = v2[u] + 0.1f * (i2[u] - v2[u]);
                i2[u] = i2[u] * 0.8f + a[u];
                bool z = vd > 0.23f;
                v2[u] = z ? 0.0f : vd;
                z2f[u] = z ? 1.0f : 0.0f;
                if (z) { int p = nA + atomicAdd(cnt, 1); dl[p] = (uint32_t)((j0 + u) << 10); }
            }
        }
        BARG();

        // ===== phase 3: layer 3 (one combined gather) + readout fold + next enc list =====
        {
            float4 bv = *(const float4*)(b3 + j0);
            unsigned long long a01 = pk2(bv.x, bv.y), a23 = pk2(bv.z, bv.w);
            unsigned long long b01 = pk2(0.f, 0.f),   b23 = pk2(0.f, 0.f);
            const int n = s_cnt1[par][r] + s_cnt2[par][r];   // o2 = z1 + z2
            gatherN(W3b, s_lh[par][r], n, a01, a23, b01, b23);
            addx2(a01, b01); addx2(a23, b23);
            float a[4]; upk2(a01, a[0], a[1]); upk2(a23, a[2], a[3]);
            float coef = c9 - c8;
            c9 *= (1.0f / 0.9f);
            c8 *= 1.25f;
#pragma unroll
            for (int u = 0; u < 4; u++) {
                float vd = v3[u] + 0.1f * (i3[u] - v3[u]);
                i3[u] = i3[u] * 0.8f + a[u];
                bool z = vd > 0.23f;
                v3[u] = z ? 0.0f : vd;
                float o3 = (z ? 1.0f : 0.0f) + z1f[u] + z2f[u];
                q[u] = fmaf(coef, o3, q[u]);
            }
            // build enc list for t+1 only while step t+1 still does real work
            if (t < T_ - 3 && g < 32) {
                uint32_t w = s_bits[r][t + 1][g];
                while (w) {
                    int b = __ffs(w) - 1; w &= w - 1;
                    int p = atomicAdd(&s_cntA[r], 1);
                    s_l1[r][p] = (uint16_t)((g << 5) | b);
                }
            }
        }
        BARG();
        par ^= 1;
    }

    // ===== step 22 epilogue: all gathers dead; spikes from local state only =====
    {
        float coef = c9 - c8;   // = 0.9 - 0.8 = 0.1
#pragma unroll
        for (int u = 0; u < 4; u++) {
            float vd1 = v1[u] + 0.1f * (i1[u] - v1[u]);
            float vd2 = v2[u] + 0.1f * (i2[u] - v2[u]);
            float vd3 = v3[u] + 0.1f * (i3[u] - v3[u]);
            float o3 = (vd1 > 0.23f ? 1.0f : 0.0f)
                     + (vd2 > 0.23f ? 1.0f : 0.0f)
                     + (vd3 > 0.23f ? 1.0f : 0.0f);
            q[u] = fmaf(coef, o3, q[u]);
        }
    }
    // step 23: output coefficient is exactly 0 -> nothing to do.

    // ---- final readout: out[b][c] = sum_k q_k * Wli[c][k] ----
    const int wig = (tid >> 5) & 1;
#pragma unroll
    for (int c = 0; c < C_; c++) {
        float4 w = *(const float4*)(Wli + c * H_ + j0);
        float s = q[0] * w.x + q[1] * w.y + q[2] * w.z + q[3] * w.w;
#pragma unroll
        for (int off = 16; off; off >>= 1)
            s += __shfl_xor_sync(0xffffffffu, s, off);
        if (lane == 0) s_part[r][wig][c] = s;
    }
    BARG();
    if (g < C_) out[(size_t)row * C_ + g] = s_part[r][0][g] + s_part[r][1][g];
}

// ============================================================
extern "C" void kernel_launch(void* const* d_in, const int* in_sizes, int n_in,
                              void* d_out, int out_size) {
    (void)in_sizes; (void)n_in; (void)out_size;
    const float* x   = (const float*)d_in[0];
    const float* W1  = (const float*)d_in[1];
    const float* b1  = (const float*)d_in[2];
    const float* W2  = (const float*)d_in[3];
    const float* b2  = (const float*)d_in[4];
    const float* W3  = (const float*)d_in[5];
    const float* b3  = (const float*)d_in[6];
    const float* Wli = (const float*)d_in[7];
    float* out = (float*)d_out;

    transpose_all<<<dim3(F_ / 32, H_ / 32, 3), dim3(32, 8)>>>(W1, W2, W3);
    snn_kernel<<<B_ / RPB, 256>>>(x, b1, b2, b3, Wli, out);
}